// round 10
// baseline (speedup 1.0000x reference)
#include <cuda_runtime.h>

#define N_ROWS  262144
#define NBINS   50
#define DCOL    512
#define D2      256             // float2 columns
#define NBLK    256             // sort blocks (1024 rows each)
#define ROWS_PB 1024
#define NACC    592             // 4 CTAs per SM exactly (148*4)
#define MAXSEG  4

// -------- device scratch --------
__device__ int    g_bhist[NBLK][NBINS];        // per-block label histograms
__device__ int    g_gbase[NBLK][NBINS];        // per-block per-bin exclusive base
__device__ int    g_off[NBINS + 1];            // bin offsets (exclusive scan)
__device__ int    g_cnt[NBINS];                // bin totals
__device__ int    g_sorted[N_ROWS];            // (bin<<18)|row, sorted by bin (stable)
__device__ float4 g_bpart[NACC][MAXSEG][D2];   // per-CTA per-segment partials
__device__ int    g_pbin [NACC][MAXSEG];       // segment bin ids (-1 = unused)

__device__ __forceinline__ int clampbin(int v) {
    return v < 0 ? 0 : (v >= NBINS ? NBINS - 1 : v);
}

// -------- K1: per-block label histograms --------
__global__ void hist_kernel(const int* __restrict__ labels) {
    __shared__ int h[NBINS];
    const int tid = threadIdx.x, blk = blockIdx.x;
    if (tid < NBINS) h[tid] = 0;
    __syncthreads();
    #pragma unroll
    for (int k = 0; k < 4; k++)
        atomicAdd(&h[clampbin(labels[blk * ROWS_PB + k * 256 + tid])], 1);
    __syncthreads();
    if (tid < NBINS) g_bhist[blk][tid] = h[tid];
}

// -------- K2: scan (per-bin block prefix + bin offsets) --------
__global__ void scan_kernel() {
    __shared__ int tot[NBINS];
    const int b = threadIdx.x;
    if (b < NBINS) {
        int run = 0;
        #pragma unroll 16
        for (int k = 0; k < NBLK; k++) {
            int h = g_bhist[k][b];
            g_gbase[k][b] = run;
            run += h;
        }
        tot[b] = run;
        g_cnt[b] = run;
    }
    __syncthreads();
    if (b == 0) {
        int off = 0;
        for (int i = 0; i < NBINS; i++) { g_off[i] = off; off += tot[i]; }
        g_off[NBINS] = off;
    }
}

// -------- K3: stable scatter (warp per block, deterministic); packs bin in hi bits ---
__global__ void scatter_kernel(const int* __restrict__ labels) {
    __shared__ int cnt[NBINS];
    const int lane = threadIdx.x, blk = blockIdx.x;
    for (int i = lane; i < NBINS; i += 32)
        cnt[i] = g_off[i] + g_gbase[blk][i];
    __syncwarp();

    for (int t = 0; t < ROWS_PB / 32; t++) {
        const int r   = blk * ROWS_PB + t * 32 + lane;
        const int lab = clampbin(labels[r]);
        unsigned mask = __match_any_sync(0xFFFFFFFFu, lab);
        const int leader = __ffs(mask) - 1;
        const int rank   = __popc(mask & ((1u << lane) - 1u));
        int base = 0;
        if (lane == leader) {
            base = cnt[lab];
            cnt[lab] = base + __popc(mask);
        }
        base = __shfl_sync(0xFFFFFFFFu, base, leader);
        g_sorted[base + rank] = r | (lab << 18);
        __syncwarp();
    }
}

// -------- K4: register-only accumulation, balanced grid, multi-segment flush --------
__global__ void __launch_bounds__(256) accum_kernel(const float* __restrict__ feats) {
    const int cta = blockIdx.x;
    const int tid = threadIdx.x;
    int p        = (int)((long long)N_ROWS * cta / NACC);
    const int p1 = (int)((long long)N_ROWS * (cta + 1) / NACC);

    const float2* __restrict__ f2 = (const float2*)feats;
    float s0 = 0.f, q0 = 0.f, s1 = 0.f, q1 = 0.f;
    int curbin = g_sorted[p] >> 18;
    int seg = 0;

    while (p < p1) {
        if (p + 8 <= p1) {
            int e[8];
            #pragma unroll
            for (int u = 0; u < 8; u++) e[u] = g_sorted[p + u];
            bool same = true;
            #pragma unroll
            for (int u = 0; u < 8; u++) same &= ((e[u] >> 18) == curbin);
            if (same) {                        // uniform branch (broadcast labels)
                float2 v[8];
                #pragma unroll
                for (int u = 0; u < 8; u++)
                    v[u] = f2[(size_t)(e[u] & 0x3FFFF) * D2 + tid];
                #pragma unroll
                for (int u = 0; u < 8; u++) {
                    s0 += v[u].x; q0 = fmaf(v[u].x, v[u].x, q0);
                    s1 += v[u].y; q1 = fmaf(v[u].y, v[u].y, q1);
                }
                p += 8;
                continue;
            }
        }
        // scalar path (bin boundary or tail)
        int e = g_sorted[p];
        int b = e >> 18;
        if (b != curbin) {
            int s = seg < MAXSEG - 1 ? seg : MAXSEG - 1;
            g_bpart[cta][s][tid] = make_float4(s0, q0, s1, q1);
            if (tid == 0) g_pbin[cta][s] = curbin;
            seg++;
            s0 = q0 = s1 = q1 = 0.f;
            curbin = b;
        }
        float2 v = f2[(size_t)(e & 0x3FFFF) * D2 + tid];
        s0 += v.x; q0 = fmaf(v.x, v.x, q0);
        s1 += v.y; q1 = fmaf(v.y, v.y, q1);
        p++;
    }
    {
        int s = seg < MAXSEG - 1 ? seg : MAXSEG - 1;
        g_bpart[cta][s][tid] = make_float4(s0, q0, s1, q1);
        if (tid == 0) g_pbin[cta][s] = curbin;
        seg++;
    }
    if (tid == 0)
        for (int s = seg; s < MAXSEG; s++) g_pbin[cta][s] = -1;
}

// -------- K5: fused finalize + smooth (4 CTAs x 64 float2-cols each) --------
extern __shared__ unsigned char fs_smem[];

__global__ void __launch_bounds__(256) finsmooth_kernel(const float* __restrict__ rmean,
                                                        const float* __restrict__ rvar,
                                                        const float* __restrict__ nst,
                                                        const float* __restrict__ kw,
                                                        float* __restrict__ out) {
    float2* smean = (float2*)fs_smem;               // [NBINS][64]
    float2* svar  = smean + NBINS * 64;             // [NBINS][64]
    const int tid = threadIdx.x;
    const int cb  = blockIdx.x;                     // column block (64 float2 cols)
    const int cl  = tid & 63;                       // local float2 col
    const int bg  = tid >> 6;                       // bin group 0..3
    const int col2 = cb * 64 + cl;                  // global float2 col 0..255

    if (cb == 0 && tid < NBINS)
        out[2 * NBINS * DCOL + tid] = nst[tid] + (float)g_cnt[tid];   // new_num

    for (int b = bg; b < NBINS; b += 4) {
        const int o0 = g_off[b], o1 = g_off[b + 1];
        float4 acc = make_float4(0.f, 0.f, 0.f, 0.f);
        if (o1 > o0) {
            int lo = (int)((long long)o0 * NACC / N_ROWS) - 1;
            int hi = (int)((long long)(o1 - 1) * NACC / N_ROWS) + 1;
            lo = lo < 0 ? 0 : lo;
            hi = hi >= NACC ? NACC - 1 : hi;
            for (int c = lo; c <= hi; c++) {
                #pragma unroll
                for (int s = 0; s < MAXSEG; s++) {
                    if (g_pbin[c][s] == b) {
                        float4 pp = g_bpart[c][s][col2];
                        acc.x += pp.x; acc.y += pp.y; acc.z += pp.z; acc.w += pp.w;
                    }
                }
            }
        }
        const float cnt    = (float)(o1 - o0);
        const float safe_n = fmaxf(cnt, 1.f);
        const float dn     = fmaxf(cnt - 1.f, 1.f);
        const float m0 = acc.x / safe_n;
        const float v0 = (acc.y - safe_n * m0 * m0) / dn;
        const float m1 = acc.z / safe_n;
        const float v1 = (acc.w - safe_n * m1 * m1) / dn;

        const int c0 = b * DCOL + 2 * col2;
        const float rm0 = rmean[c0], rm1 = rmean[c0 + 1];
        const float rv0 = rvar[c0],  rv1 = rvar[c0 + 1];
        const bool present = cnt > 0.f;
        const float f = 0.9f, g1 = 0.1f;

        float2 nm = make_float2(present ? g1 * m0 + f * rm0 : rm0,
                                present ? g1 * m1 + f * rm1 : rm1);
        float2 nv = make_float2(present ? g1 * v0 + f * rv0 : rv0,
                                present ? g1 * v1 + f * rv1 : rv1);

        ((float2*)out)[c0 / 2]                  = nm;   // new_mean
        ((float2*)(out + NBINS * DCOL))[c0 / 2] = nv;   // new_var
        smean[b * 64 + cl] = nm;
        svar [b * 64 + cl] = nv;
    }
    __syncthreads();

    const float wk[5] = {kw[0], kw[1], kw[2], kw[3], kw[4]};
    for (int b = bg; b < NBINS; b += 4) {
        float2 sm = make_float2(0.f, 0.f), sv = make_float2(0.f, 0.f);
        #pragma unroll
        for (int k = 0; k < 5; k++) {
            int m = b + k - 2;
            if (m < 0)      m = -m;                  // reflect101 left
            if (m >= NBINS) m = 2 * (NBINS - 1) - m; // reflect101 right
            float2 a = smean[m * 64 + cl];
            float2 c = svar [m * 64 + cl];
            sm.x = fmaf(wk[k], a.x, sm.x); sm.y = fmaf(wk[k], a.y, sm.y);
            sv.x = fmaf(wk[k], c.x, sv.x); sv.y = fmaf(wk[k], c.y, sv.y);
        }
        const int base = 2 * NBINS * DCOL + NBINS;   // 51250
        const int c0   = b * DCOL + 2 * col2;
        ((float2*)(out + base))[c0 / 2]               = sm;  // smoothed_mean
        ((float2*)(out + base + NBINS * DCOL))[c0 / 2] = sv; // smoothed_var
    }
}

// -------- launch --------
extern "C" void kernel_launch(void* const* d_in, const int* in_sizes, int n_in,
                              void* d_out, int out_size) {
    const float* feats  = (const float*)d_in[0];
    const int*   labels = (const int*)d_in[1];
    const float* rmean  = (const float*)d_in[2];
    const float* rvar   = (const float*)d_in[3];
    const float* nst    = (const float*)d_in[4];
    const float* kw     = (const float*)d_in[5];
    float*       out    = (float*)d_out;

    const size_t fs_bytes = (size_t)NBINS * 64 * sizeof(float2) * 2;   // 51200 B
    cudaFuncSetAttribute(finsmooth_kernel, cudaFuncAttributeMaxDynamicSharedMemorySize,
                         (int)fs_bytes);

    hist_kernel<<<NBLK, 256>>>(labels);
    scan_kernel<<<1, 64>>>();
    scatter_kernel<<<NBLK, 32>>>(labels);
    accum_kernel<<<NACC, 256>>>(feats);
    finsmooth_kernel<<<4, 256, fs_bytes>>>(rmean, rvar, nst, kw, out);
}

// round 11
// speedup vs baseline: 1.5102x; 1.5102x over previous
#include <cuda_runtime.h>

#define N_ROWS  262144
#define NBINS   50
#define DCOL    512
#define D2      256             // float2 columns
#define NBLK    256             // sort blocks (1024 rows each)
#define ROWS_PB 1024
#define SCH     16              // chunks per bin
#define NACC    (NBINS * SCH)   // 800 accum CTAs (all co-resident at 6/SM)

// -------- device scratch --------
__device__ int    g_bhist[NBLK][NBINS];    // per-block label histograms
__device__ int    g_gbase[NBLK][NBINS];    // per-block per-bin exclusive base
__device__ int    g_off[NBINS + 1];        // bin offsets (exclusive scan)
__device__ int    g_cnt[NBINS];            // bin totals
__device__ int    g_sorted[N_ROWS];        // row indices sorted by bin (stable)
__device__ float4 g_bpart[NACC][D2];       // per-CTA partials {s0,q0,s1,q1}

__device__ __forceinline__ int clampbin(int v) {
    return v < 0 ? 0 : (v >= NBINS ? NBINS - 1 : v);
}

// -------- K1: per-block label histograms --------
__global__ void hist_kernel(const int* __restrict__ labels) {
    __shared__ int h[NBINS];
    const int tid = threadIdx.x, blk = blockIdx.x;
    if (tid < NBINS) h[tid] = 0;
    __syncthreads();
    #pragma unroll
    for (int k = 0; k < 4; k++)
        atomicAdd(&h[clampbin(labels[blk * ROWS_PB + k * 256 + tid])], 1);
    __syncthreads();
    if (tid < NBINS) g_bhist[blk][tid] = h[tid];
}

// -------- K2: scan (per-bin block prefix + bin offsets) --------
__global__ void scan_kernel() {
    __shared__ int tot[NBINS];
    const int b = threadIdx.x;
    if (b < NBINS) {
        int run = 0;
        #pragma unroll 16
        for (int k = 0; k < NBLK; k++) {
            int h = g_bhist[k][b];
            g_gbase[k][b] = run;
            run += h;
        }
        tot[b] = run;
        g_cnt[b] = run;
    }
    __syncthreads();
    if (b == 0) {
        int off = 0;
        for (int i = 0; i < NBINS; i++) { g_off[i] = off; off += tot[i]; }
        g_off[NBINS] = off;
    }
}

// -------- K3: stable scatter (warp per block, deterministic) --------
__global__ void scatter_kernel(const int* __restrict__ labels) {
    __shared__ int cnt[NBINS];
    const int lane = threadIdx.x, blk = blockIdx.x;
    for (int i = lane; i < NBINS; i += 32)
        cnt[i] = g_off[i] + g_gbase[blk][i];
    __syncwarp();

    for (int t = 0; t < ROWS_PB / 32; t++) {
        const int r   = blk * ROWS_PB + t * 32 + lane;
        const int lab = clampbin(labels[r]);
        unsigned mask = __match_any_sync(0xFFFFFFFFu, lab);
        const int leader = __ffs(mask) - 1;
        const int rank   = __popc(mask & ((1u << lane) - 1u));
        int base = 0;
        if (lane == leader) {
            base = cnt[lab];
            cnt[lab] = base + __popc(mask);
        }
        base = __shfl_sync(0xFFFFFFFFu, base, leader);
        g_sorted[base + rank] = r;
        __syncwarp();
    }
}

// -------- K4: register-only accumulation, one bin per CTA, idx-ahead prefetch ----
__global__ void __launch_bounds__(256, 6) accum_kernel(const float* __restrict__ feats) {
    const int b   = blockIdx.x / SCH;
    const int j   = blockIdx.x % SCH;
    const int o0  = g_off[b];
    const int len = g_off[b + 1] - o0;
    const int p0  = o0 + (int)((long long)len * j / SCH);
    const int p1  = o0 + (int)((long long)len * (j + 1) / SCH);
    const int tid = threadIdx.x;

    const float2* __restrict__ f2 = (const float2*)feats;
    float s0 = 0.f, q0 = 0.f, s1 = 0.f, q1 = 0.f;

    int p = p0;
    int idx[8];
    const int nfull = (p1 - p0) / 8;       // full 8-row groups
    if (nfull > 0) {
        #pragma unroll
        for (int u = 0; u < 8; u++) idx[u] = g_sorted[p + u];
    }
    for (int it = 0; it < nfull; it++) {
        // issue 8 independent gathers from the already-known indices
        float2 v[8];
        #pragma unroll
        for (int u = 0; u < 8; u++) v[u] = f2[(size_t)idx[u] * D2 + tid];

        // prefetch next group's indices while gathers are in flight
        if (it + 1 < nfull) {
            #pragma unroll
            for (int u = 0; u < 8; u++) idx[u] = g_sorted[p + 8 + u];
        }

        #pragma unroll
        for (int u = 0; u < 8; u++) {
            s0 += v[u].x; q0 = fmaf(v[u].x, v[u].x, q0);
            s1 += v[u].y; q1 = fmaf(v[u].y, v[u].y, q1);
        }
        p += 8;
    }
    for (; p < p1; p++) {
        float2 v = f2[(size_t)g_sorted[p] * D2 + tid];
        s0 += v.x; q0 = fmaf(v.x, v.x, q0);
        s1 += v.y; q1 = fmaf(v.y, v.y, q1);
    }
    g_bpart[blockIdx.x][tid] = make_float4(s0, q0, s1, q1);
}

// -------- K5: reduce partials, EMA update, write new_mean/new_var/new_num --------
__global__ void finalize_kernel(const float* __restrict__ rmean,
                                const float* __restrict__ rvar,
                                const float* __restrict__ nst,
                                float* __restrict__ out) {
    const int idx = blockIdx.x * blockDim.x + threadIdx.x;   // 0 .. NBINS*D2-1
    if (idx < NBINS)
        out[2 * NBINS * DCOL + idx] = nst[idx] + (float)g_cnt[idx];   // new_num
    if (idx >= NBINS * D2) return;

    const int b = idx / D2;
    const int c = idx - b * D2;

    float4 acc = make_float4(0.f, 0.f, 0.f, 0.f);
    #pragma unroll
    for (int j = 0; j < SCH; j++) {
        float4 p = g_bpart[b * SCH + j][c];
        acc.x += p.x; acc.y += p.y; acc.z += p.z; acc.w += p.w;
    }

    const float cnt    = (float)g_cnt[b];
    const float safe_n = fmaxf(cnt, 1.f);
    const float dn     = fmaxf(cnt - 1.f, 1.f);
    const float m0 = acc.x / safe_n;
    const float v0 = (acc.y - safe_n * m0 * m0) / dn;
    const float m1 = acc.z / safe_n;
    const float v1 = (acc.w - safe_n * m1 * m1) / dn;

    const int c0 = b * DCOL + 2 * c;
    const float rm0 = rmean[c0], rm1 = rmean[c0 + 1];
    const float rv0 = rvar[c0],  rv1 = rvar[c0 + 1];
    const bool present = cnt > 0.f;
    const float f = 0.9f, g1 = 0.1f;

    float nm0 = present ? g1 * m0 + f * rm0 : rm0;
    float nm1 = present ? g1 * m1 + f * rm1 : rm1;
    float nv0 = present ? g1 * v0 + f * rv0 : rv0;
    float nv1 = present ? g1 * v1 + f * rv1 : rv1;

    ((float2*)out)[c0 / 2]                  = make_float2(nm0, nm1);  // new_mean
    ((float2*)(out + NBINS * DCOL))[c0 / 2] = make_float2(nv0, nv1);  // new_var
}

// -------- K6: 5-tap reflect-101 smoothing over the bin axis --------
__global__ void smooth_kernel(const float* __restrict__ w, float* __restrict__ out) {
    const int idx = blockIdx.x * blockDim.x + threadIdx.x;   // 0 .. NBINS*DCOL-1
    if (idx >= NBINS * DCOL) return;
    const int bin = idx / DCOL;
    const int c   = idx - bin * DCOL;

    const float wk[5] = {w[0], w[1], w[2], w[3], w[4]};
    float sm = 0.f, sv = 0.f;
    #pragma unroll
    for (int k = 0; k < 5; k++) {
        int m = bin + k - 2;
        if (m < 0)       m = -m;                  // reflect101 left
        if (m >= NBINS)  m = 2 * (NBINS - 1) - m; // reflect101 right
        sm = fmaf(wk[k], out[m * DCOL + c], sm);
        sv = fmaf(wk[k], out[NBINS * DCOL + m * DCOL + c], sv);
    }
    const int base = 2 * NBINS * DCOL + NBINS;    // 51250
    out[base + idx]                = sm;          // smoothed_mean
    out[base + NBINS * DCOL + idx] = sv;          // smoothed_var
}

// -------- launch --------
extern "C" void kernel_launch(void* const* d_in, const int* in_sizes, int n_in,
                              void* d_out, int out_size) {
    const float* feats  = (const float*)d_in[0];
    const int*   labels = (const int*)d_in[1];
    const float* rmean  = (const float*)d_in[2];
    const float* rvar   = (const float*)d_in[3];
    const float* nst    = (const float*)d_in[4];
    const float* kw     = (const float*)d_in[5];
    float*       out    = (float*)d_out;

    hist_kernel<<<NBLK, 256>>>(labels);
    scan_kernel<<<1, 64>>>();
    scatter_kernel<<<NBLK, 32>>>(labels);
    accum_kernel<<<NACC, 256>>>(feats);
    finalize_kernel<<<(NBINS * D2 + 255) / 256, 256>>>(rmean, rvar, nst, out);
    smooth_kernel<<<(NBINS * DCOL + 255) / 256, 256>>>(kw, out);
}

// round 12
// speedup vs baseline: 1.8114x; 1.1994x over previous
#include <cuda_runtime.h>

#define N_ROWS  262144
#define NBINS   50
#define DCOL    512
#define D2      256             // float2 columns
#define NBLK    256             // sort blocks (1024 rows each)
#define ROWS_PB 1024
#define SCH     16              // chunks per bin
#define NACC    (NBINS * SCH)   // 800 accum CTAs

// -------- device scratch --------
__device__ int    g_bhist[NBLK][NBINS];    // per-block label histograms
__device__ int    g_off[NBINS + 1];        // bin offsets (written by scatter blk 0)
__device__ int    g_cnt[NBINS];            // bin totals   (written by scatter blk 0)
__device__ int    g_sorted[N_ROWS];        // row indices sorted by bin (stable)
__device__ float4 g_bpart[NACC][D2];       // per-CTA partials {s0,q0,s1,q1}

__device__ __forceinline__ int clampbin(int v) {
    return v < 0 ? 0 : (v >= NBINS ? NBINS - 1 : v);
}

// -------- K1: per-block label histograms --------
__global__ void hist_kernel(const int* __restrict__ labels) {
    __shared__ int h[NBINS];
    const int tid = threadIdx.x, blk = blockIdx.x;
    if (tid < NBINS) h[tid] = 0;
    __syncthreads();
    #pragma unroll
    for (int k = 0; k < 4; k++)
        atomicAdd(&h[clampbin(labels[blk * ROWS_PB + k * 256 + tid])], 1);
    __syncthreads();
    if (tid < NBINS) g_bhist[blk][tid] = h[tid];
}

// -------- K2: scatter with inline scan (every block recomputes the prefix) --------
__global__ void __launch_bounds__(64) scatter_kernel(const int* __restrict__ labels) {
    __shared__ int stot[NBINS];   // bin totals
    __shared__ int sgb [NBINS];   // this block's per-bin exclusive base
    __shared__ int soff[NBINS + 1];
    __shared__ int cnt [NBINS];   // running write cursor
    const int tid = threadIdx.x, blk = blockIdx.x;

    // per-bin scan over chunks (threads 0..49; independent loads, L2-resident)
    if (tid < NBINS) {
        int run = 0, gb = 0;
        #pragma unroll 16
        for (int k = 0; k < NBLK; k++) {
            int h = g_bhist[k][tid];
            if (k == blk) gb = run;
            run += h;
        }
        stot[tid] = run;
        sgb[tid]  = gb;
    }
    __syncthreads();
    if (tid == 0) {
        int off = 0;
        #pragma unroll
        for (int b = 0; b < NBINS; b++) { soff[b] = off; off += stot[b]; }
        soff[NBINS] = off;
    }
    __syncthreads();
    if (tid < NBINS) {
        cnt[tid] = soff[tid] + sgb[tid];
        if (blk == 0) {                     // publish offsets for accum/finsmooth
            g_off[tid] = soff[tid];
            g_cnt[tid] = stot[tid];
            if (tid == 0) g_off[NBINS] = soff[NBINS];
        }
    }
    __syncthreads();

    // warp 0: stable scatter of this block's 1024 rows
    if (tid < 32) {
        const int lane = tid;
        for (int t = 0; t < ROWS_PB / 32; t++) {
            const int r   = blk * ROWS_PB + t * 32 + lane;
            const int lab = clampbin(labels[r]);
            unsigned mask = __match_any_sync(0xFFFFFFFFu, lab);
            const int leader = __ffs(mask) - 1;
            const int rank   = __popc(mask & ((1u << lane) - 1u));
            int base = 0;
            if (lane == leader) {
                base = cnt[lab];
                cnt[lab] = base + __popc(mask);
            }
            base = __shfl_sync(0xFFFFFFFFu, base, leader);
            g_sorted[base + rank] = r;
            __syncwarp();
        }
    }
}

// -------- K3: register-only accumulation, one bin per CTA, idx-ahead prefetch ----
__global__ void __launch_bounds__(256, 6) accum_kernel(const float* __restrict__ feats) {
    const int b   = blockIdx.x / SCH;
    const int j   = blockIdx.x % SCH;
    const int o0  = g_off[b];
    const int len = g_off[b + 1] - o0;
    const int p0  = o0 + (int)((long long)len * j / SCH);
    const int p1  = o0 + (int)((long long)len * (j + 1) / SCH);
    const int tid = threadIdx.x;

    const float2* __restrict__ f2 = (const float2*)feats;
    float s0 = 0.f, q0 = 0.f, s1 = 0.f, q1 = 0.f;

    int p = p0;
    int idx[8];
    const int nfull = (p1 - p0) / 8;
    if (nfull > 0) {
        #pragma unroll
        for (int u = 0; u < 8; u++) idx[u] = g_sorted[p + u];
    }
    for (int it = 0; it < nfull; it++) {
        float2 v[8];
        #pragma unroll
        for (int u = 0; u < 8; u++) v[u] = f2[(size_t)idx[u] * D2 + tid];

        if (it + 1 < nfull) {
            #pragma unroll
            for (int u = 0; u < 8; u++) idx[u] = g_sorted[p + 8 + u];
        }

        #pragma unroll
        for (int u = 0; u < 8; u++) {
            s0 += v[u].x; q0 = fmaf(v[u].x, v[u].x, q0);
            s1 += v[u].y; q1 = fmaf(v[u].y, v[u].y, q1);
        }
        p += 8;
    }
    for (; p < p1; p++) {
        float2 v = f2[(size_t)g_sorted[p] * D2 + tid];
        s0 += v.x; q0 = fmaf(v.x, v.x, q0);
        s1 += v.y; q1 = fmaf(v.y, v.y, q1);
    }
    g_bpart[blockIdx.x][tid] = make_float4(s0, q0, s1, q1);
}

// -------- K4: fused finalize + smooth (one CTA per bin; redundant window reduce) --
__global__ void __launch_bounds__(256) finsmooth_kernel(const float* __restrict__ rmean,
                                                        const float* __restrict__ rvar,
                                                        const float* __restrict__ nst,
                                                        const float* __restrict__ kw,
                                                        float* __restrict__ out) {
    const int b = blockIdx.x;       // bin 0..49
    const int c = threadIdx.x;      // float4 col 0..255 (covers float cols 2c,2c+1)

    if (b == 0 && c < NBINS)
        out[2 * NBINS * DCOL + c] = nst[c] + (float)g_cnt[c];   // new_num

    const float wk[5] = {kw[0], kw[1], kw[2], kw[3], kw[4]};
    const float f = 0.9f, g1 = 0.1f;

    float sm0 = 0.f, sm1 = 0.f, sv0 = 0.f, sv1 = 0.f;

    #pragma unroll
    for (int w = 0; w < 5; w++) {
        int m = b + w - 2;
        if (m < 0)      m = -m;                   // reflect101 left
        if (m >= NBINS) m = 2 * (NBINS - 1) - m;  // reflect101 right

        float4 acc = make_float4(0.f, 0.f, 0.f, 0.f);
        #pragma unroll
        for (int j = 0; j < SCH; j++) {
            float4 p = g_bpart[m * SCH + j][c];
            acc.x += p.x; acc.y += p.y; acc.z += p.z; acc.w += p.w;
        }

        const float cnt    = (float)g_cnt[m];
        const float safe_n = fmaxf(cnt, 1.f);
        const float dn     = fmaxf(cnt - 1.f, 1.f);
        const float mm0 = acc.x / safe_n;
        const float vv0 = (acc.y - safe_n * mm0 * mm0) / dn;
        const float mm1 = acc.z / safe_n;
        const float vv1 = (acc.w - safe_n * mm1 * mm1) / dn;

        const int c0 = m * DCOL + 2 * c;
        const float rm0 = rmean[c0], rm1 = rmean[c0 + 1];
        const float rv0 = rvar[c0],  rv1 = rvar[c0 + 1];
        const bool present = cnt > 0.f;

        const float nm0 = present ? g1 * mm0 + f * rm0 : rm0;
        const float nm1 = present ? g1 * mm1 + f * rm1 : rm1;
        const float nv0 = present ? g1 * vv0 + f * rv0 : rv0;
        const float nv1 = present ? g1 * vv1 + f * rv1 : rv1;

        if (w == 2) {   // m == b: write this bin's new_mean / new_var
            ((float2*)out)[c0 / 2]                  = make_float2(nm0, nm1);
            ((float2*)(out + NBINS * DCOL))[c0 / 2] = make_float2(nv0, nv1);
        }

        sm0 = fmaf(wk[w], nm0, sm0); sm1 = fmaf(wk[w], nm1, sm1);
        sv0 = fmaf(wk[w], nv0, sv0); sv1 = fmaf(wk[w], nv1, sv1);
    }

    const int base = 2 * NBINS * DCOL + NBINS;    // 51250
    const int c0   = b * DCOL + 2 * c;
    ((float2*)(out + base))[c0 / 2]                = make_float2(sm0, sm1); // smoothed_mean
    ((float2*)(out + base + NBINS * DCOL))[c0 / 2] = make_float2(sv0, sv1); // smoothed_var
}

// -------- launch --------
extern "C" void kernel_launch(void* const* d_in, const int* in_sizes, int n_in,
                              void* d_out, int out_size) {
    const float* feats  = (const float*)d_in[0];
    const int*   labels = (const int*)d_in[1];
    const float* rmean  = (const float*)d_in[2];
    const float* rvar   = (const float*)d_in[3];
    const float* nst    = (const float*)d_in[4];
    const float* kw     = (const float*)d_in[5];
    float*       out    = (float*)d_out;

    hist_kernel<<<NBLK, 256>>>(labels);
    scatter_kernel<<<NBLK, 64>>>(labels);
    accum_kernel<<<NACC, 256>>>(feats);
    finsmooth_kernel<<<NBINS, 256>>>(rmean, rvar, nst, kw, out);
}

// round 13
// speedup vs baseline: 1.8988x; 1.0483x over previous
#include <cuda_runtime.h>

#define N_ROWS  262144
#define NBINS   50
#define DCOL    512
#define D2      256             // float2 columns
#define NBLK    256             // sort blocks (1024 rows each)
#define ROWS_PB 1024
#define SCH     16              // chunks per bin
#define NACC    (NBINS * SCH)   // 800 accum CTAs
#define CG      4               // finsmooth column groups (64 float4 cols each)

// -------- device scratch --------
__device__ int    g_bhist[NBLK][NBINS];    // per-block label histograms
__device__ int    g_off[NBINS + 1];        // bin offsets (written by scatter blk 0)
__device__ int    g_cnt[NBINS];            // bin totals   (written by scatter blk 0)
__device__ int    g_sorted[N_ROWS];        // row indices sorted by bin (stable)
__device__ float4 g_bpart[NACC][D2];       // per-CTA partials {s0,q0,s1,q1}

__device__ __forceinline__ int clampbin(int v) {
    return v < 0 ? 0 : (v >= NBINS ? NBINS - 1 : v);
}

// -------- K1: per-block label histograms --------
__global__ void hist_kernel(const int* __restrict__ labels) {
    __shared__ int h[NBINS];
    const int tid = threadIdx.x, blk = blockIdx.x;
    if (tid < NBINS) h[tid] = 0;
    __syncthreads();
    #pragma unroll
    for (int k = 0; k < 4; k++)
        atomicAdd(&h[clampbin(labels[blk * ROWS_PB + k * 256 + tid])], 1);
    __syncthreads();
    if (tid < NBINS) g_bhist[blk][tid] = h[tid];
}

// -------- K2: scatter with inline scan (every block recomputes the prefix) --------
__global__ void __launch_bounds__(64) scatter_kernel(const int* __restrict__ labels) {
    __shared__ int stot[NBINS];   // bin totals
    __shared__ int sgb [NBINS];   // this block's per-bin exclusive base
    __shared__ int soff[NBINS + 1];
    __shared__ int cnt [NBINS];   // running write cursor
    const int tid = threadIdx.x, blk = blockIdx.x;

    if (tid < NBINS) {
        int run = 0, gb = 0;
        #pragma unroll 16
        for (int k = 0; k < NBLK; k++) {
            int h = g_bhist[k][tid];
            if (k == blk) gb = run;
            run += h;
        }
        stot[tid] = run;
        sgb[tid]  = gb;
    }
    __syncthreads();
    if (tid == 0) {
        int off = 0;
        #pragma unroll
        for (int b = 0; b < NBINS; b++) { soff[b] = off; off += stot[b]; }
        soff[NBINS] = off;
    }
    __syncthreads();
    if (tid < NBINS) {
        cnt[tid] = soff[tid] + sgb[tid];
        if (blk == 0) {
            g_off[tid] = soff[tid];
            g_cnt[tid] = stot[tid];
            if (tid == 0) g_off[NBINS] = soff[NBINS];
        }
    }
    __syncthreads();

    if (tid < 32) {
        const int lane = tid;
        for (int t = 0; t < ROWS_PB / 32; t++) {
            const int r   = blk * ROWS_PB + t * 32 + lane;
            const int lab = clampbin(labels[r]);
            unsigned mask = __match_any_sync(0xFFFFFFFFu, lab);
            const int leader = __ffs(mask) - 1;
            const int rank   = __popc(mask & ((1u << lane) - 1u));
            int base = 0;
            if (lane == leader) {
                base = cnt[lab];
                cnt[lab] = base + __popc(mask);
            }
            base = __shfl_sync(0xFFFFFFFFu, base, leader);
            g_sorted[base + rank] = r;
            __syncwarp();
        }
    }
}

// -------- K3: register-only accumulation, one bin per CTA, idx-ahead prefetch ----
__global__ void __launch_bounds__(256, 6) accum_kernel(const float* __restrict__ feats) {
    const int b   = blockIdx.x / SCH;
    const int j   = blockIdx.x % SCH;
    const int o0  = g_off[b];
    const int len = g_off[b + 1] - o0;
    const int p0  = o0 + (int)((long long)len * j / SCH);
    const int p1  = o0 + (int)((long long)len * (j + 1) / SCH);
    const int tid = threadIdx.x;

    const float2* __restrict__ f2 = (const float2*)feats;
    float s0 = 0.f, q0 = 0.f, s1 = 0.f, q1 = 0.f;

    int p = p0;
    int idx[8];
    const int nfull = (p1 - p0) / 8;
    if (nfull > 0) {
        #pragma unroll
        for (int u = 0; u < 8; u++) idx[u] = g_sorted[p + u];
    }
    for (int it = 0; it < nfull; it++) {
        float2 v[8];
        #pragma unroll
        for (int u = 0; u < 8; u++) v[u] = f2[(size_t)idx[u] * D2 + tid];

        if (it + 1 < nfull) {
            #pragma unroll
            for (int u = 0; u < 8; u++) idx[u] = g_sorted[p + 8 + u];
        }

        #pragma unroll
        for (int u = 0; u < 8; u++) {
            s0 += v[u].x; q0 = fmaf(v[u].x, v[u].x, q0);
            s1 += v[u].y; q1 = fmaf(v[u].y, v[u].y, q1);
        }
        p += 8;
    }
    for (; p < p1; p++) {
        float2 v = f2[(size_t)g_sorted[p] * D2 + tid];
        s0 += v.x; q0 = fmaf(v.x, v.x, q0);
        s1 += v.y; q1 = fmaf(v.y, v.y, q1);
    }
    g_bpart[blockIdx.x][tid] = make_float4(s0, q0, s1, q1);
}

// -------- K4: fused finalize + smooth, parallel windows --------
// grid = 50 bins x CG colgroups; block = 320 = 5 windows x 64 cols
__global__ void __launch_bounds__(320) finsmooth_kernel(const float* __restrict__ rmean,
                                                        const float* __restrict__ rvar,
                                                        const float* __restrict__ nst,
                                                        const float* __restrict__ kw,
                                                        float* __restrict__ out) {
    __shared__ float4 sred[5][64];          // {nm0, nm1, nv0, nv1} per window/col

    const int b    = blockIdx.x / CG;       // bin
    const int cg   = blockIdx.x % CG;       // column group
    const int tid  = threadIdx.x;
    const int w    = tid / 64;              // window 0..4
    const int cl   = tid % 64;              // local float4 col
    const int col4 = cg * 64 + cl;          // global float4 col 0..255

    if (blockIdx.x == 0 && tid < NBINS)
        out[2 * NBINS * DCOL + tid] = nst[tid] + (float)g_cnt[tid];   // new_num

    int m = b + w - 2;
    if (m < 0)      m = -m;                   // reflect101 left
    if (m >= NBINS) m = 2 * (NBINS - 1) - m;  // reflect101 right

    // reduce 16 chunk partials for (window bin m, col4)
    float4 acc = make_float4(0.f, 0.f, 0.f, 0.f);
    #pragma unroll
    for (int j = 0; j < SCH; j++) {
        float4 p = g_bpart[m * SCH + j][col4];
        acc.x += p.x; acc.y += p.y; acc.z += p.z; acc.w += p.w;
    }

    const float cnt    = (float)g_cnt[m];
    const float safe_n = fmaxf(cnt, 1.f);
    const float dn     = fmaxf(cnt - 1.f, 1.f);
    const float mm0 = acc.x / safe_n;
    const float vv0 = (acc.y - safe_n * mm0 * mm0) / dn;
    const float mm1 = acc.z / safe_n;
    const float vv1 = (acc.w - safe_n * mm1 * mm1) / dn;

    const int c0 = m * DCOL + 2 * col4;
    const float rm0 = rmean[c0], rm1 = rmean[c0 + 1];
    const float rv0 = rvar[c0],  rv1 = rvar[c0 + 1];
    const bool present = cnt > 0.f;
    const float f = 0.9f, g1 = 0.1f;

    const float nm0 = present ? g1 * mm0 + f * rm0 : rm0;
    const float nm1 = present ? g1 * mm1 + f * rm1 : rm1;
    const float nv0 = present ? g1 * vv0 + f * rv0 : rv0;
    const float nv1 = present ? g1 * vv1 + f * rv1 : rv1;

    if (w == 2) {   // m == b: write this bin's new_mean / new_var
        ((float2*)out)[c0 / 2]                  = make_float2(nm0, nm1);
        ((float2*)(out + NBINS * DCOL))[c0 / 2] = make_float2(nv0, nv1);
    }

    sred[w][cl] = make_float4(nm0, nm1, nv0, nv1);
    __syncthreads();

    if (w == 0) {
        const float wk[5] = {kw[0], kw[1], kw[2], kw[3], kw[4]};
        float sm0 = 0.f, sm1 = 0.f, sv0 = 0.f, sv1 = 0.f;
        #pragma unroll
        for (int k = 0; k < 5; k++) {
            float4 r = sred[k][cl];
            sm0 = fmaf(wk[k], r.x, sm0); sm1 = fmaf(wk[k], r.y, sm1);
            sv0 = fmaf(wk[k], r.z, sv0); sv1 = fmaf(wk[k], r.w, sv1);
        }
        const int base = 2 * NBINS * DCOL + NBINS;    // 51250
        const int o0   = b * DCOL + 2 * col4;
        ((float2*)(out + base))[o0 / 2]                = make_float2(sm0, sm1); // smoothed_mean
        ((float2*)(out + base + NBINS * DCOL))[o0 / 2] = make_float2(sv0, sv1); // smoothed_var
    }
}

// -------- launch --------
extern "C" void kernel_launch(void* const* d_in, const int* in_sizes, int n_in,
                              void* d_out, int out_size) {
    const float* feats  = (const float*)d_in[0];
    const int*   labels = (const int*)d_in[1];
    const float* rmean  = (const float*)d_in[2];
    const float* rvar   = (const float*)d_in[3];
    const float* nst    = (const float*)d_in[4];
    const float* kw     = (const float*)d_in[5];
    float*       out    = (float*)d_out;

    hist_kernel<<<NBLK, 256>>>(labels);
    scatter_kernel<<<NBLK, 64>>>(labels);
    accum_kernel<<<NACC, 256>>>(feats);
    finsmooth_kernel<<<NBINS * CG, 320>>>(rmean, rvar, nst, kw, out);
}